// round 3
// baseline (speedup 1.0000x reference)
#include <cuda_runtime.h>
#include <math.h>

#define N_NODES 100000
#define N_EDGES 800000
#define NB_SCAN ((N_NODES + 255) / 256)   // 391

// ---- static device scratch (no allocations allowed) ----
__device__ int   g_is32;                 // 1 if edge_index delivered as int32
__device__ int   g_cnt [N_NODES];
__device__ int   g_off [N_NODES + 1];
__device__ int   g_cur [N_NODES];
__device__ int   g_srcl[N_EDGES];        // sources grouped by dst (CSR)
__device__ float g_dinv[N_NODES];
__device__ float g_h1  [N_NODES * 64];   // layer-1 pre-agg features
__device__ float g_hid [N_NODES * 64];   // relu'd hidden (layer-2 input)
__device__ float g_h2  [N_NODES * 40];   // layer-2 pre-agg features
__device__ int   g_bsum[512];
__device__ int   g_boff[512];

// ---------------------------------------------------------------------------
// dtype detection: int64 edge values < 2^31 have zero high words; int32 layout
// puts real edge indices (mostly nonzero) in those slots.
// ---------------------------------------------------------------------------
__global__ void k_detect(const unsigned* __restrict__ ei_raw) {
    unsigned v = ei_raw[2 * threadIdx.x + 1];   // hypothetical int64 high word
#pragma unroll
    for (int o = 16; o; o >>= 1) v |= __shfl_xor_sync(0xffffffffu, v, o);
    if (threadIdx.x == 0) g_is32 = (v != 0) ? 1 : 0;
}

__device__ __forceinline__ int edge_at(const void* ei, int idx) {
    if (g_is32) return ((const int*)ei)[idx];
    return (int)((const long long*)ei)[idx];
}

// ---------------------------------------------------------------------------
// CSR build
// ---------------------------------------------------------------------------
__global__ void k_zero_cnt() {
    int i = blockIdx.x * blockDim.x + threadIdx.x;
    if (i < N_NODES) g_cnt[i] = 0;
}

__global__ void k_count(const void* __restrict__ ei) {
    int e = blockIdx.x * blockDim.x + threadIdx.x;
    if (e >= N_EDGES) return;
    int d = edge_at(ei, N_EDGES + e);
    if ((unsigned)d < N_NODES) atomicAdd(&g_cnt[d], 1);
}

// level-1 scan: 256 nodes per block, write per-block exclusive + block sums
__global__ void k_scan1() {
    int i = blockIdx.x * 256 + threadIdx.x;
    int lane = threadIdx.x & 31, wid = threadIdx.x >> 5;
    int v = (i < N_NODES) ? g_cnt[i] : 0;
    int x = v;
#pragma unroll
    for (int o = 1; o < 32; o <<= 1) {
        int y = __shfl_up_sync(0xffffffffu, x, o);
        if (lane >= o) x += y;
    }
    __shared__ int ws[8];
    if (lane == 31) ws[wid] = x;
    __syncthreads();
    if (wid == 0) {
        int s = (lane < 8) ? ws[lane] : 0;
#pragma unroll
        for (int o = 1; o < 8; o <<= 1) {
            int y = __shfl_up_sync(0xffffffffu, s, o);
            if (lane >= o) s += y;
        }
        if (lane < 8) ws[lane] = s;
    }
    __syncthreads();
    int incl = x + (wid ? ws[wid - 1] : 0);
    if (i < N_NODES) g_off[i] = incl - v;
    if (threadIdx.x == 255) g_bsum[blockIdx.x] = incl;
}

// level-2 scan: single block over NB_SCAN block sums
__global__ void k_scan2() {
    int t = threadIdx.x, lane = t & 31, wid = t >> 5;
    int v = (t < NB_SCAN) ? g_bsum[t] : 0;
    int x = v;
#pragma unroll
    for (int o = 1; o < 32; o <<= 1) {
        int y = __shfl_up_sync(0xffffffffu, x, o);
        if (lane >= o) x += y;
    }
    __shared__ int ws[16];
    if (lane == 31) ws[wid] = x;
    __syncthreads();
    if (wid == 0) {
        int s = (lane < 16) ? ws[lane] : 0;
#pragma unroll
        for (int o = 1; o < 16; o <<= 1) {
            int y = __shfl_up_sync(0xffffffffu, s, o);
            if (lane >= o) s += y;
        }
        if (lane < 16) ws[lane] = s;
    }
    __syncthreads();
    int incl = x + (wid ? ws[wid - 1] : 0);
    if (t < 512) g_boff[t] = incl - v;
}

// finalize offsets, bump cursors, dinv
__global__ void k_scan3() {
    int i = blockIdx.x * blockDim.x + threadIdx.x;
    if (i < N_NODES) {
        int o = g_off[i] + g_boff[i >> 8];
        g_off[i] = o;
        g_cur[i] = o;
        g_dinv[i] = rsqrtf((float)g_cnt[i] + 1.0f);
    }
    if (i == 0) g_off[N_NODES] = N_EDGES;
}

__global__ void k_fill(const void* __restrict__ ei) {
    int e = blockIdx.x * blockDim.x + threadIdx.x;
    if (e >= N_EDGES) return;
    int s = edge_at(ei, e);
    int d = edge_at(ei, N_EDGES + e);
    if ((unsigned)d >= N_NODES || (unsigned)s >= N_NODES) return;
    int p = atomicAdd(&g_cur[d], 1);
    if ((unsigned)p < N_EDGES) g_srcl[p] = s;
}

// ---------------------------------------------------------------------------
// GEMM body: Y[n,FOUT] = X[n,64] @ W[64,FOUT], 64x64 tile per block
// ---------------------------------------------------------------------------
template <int FOUT>
__device__ __forceinline__ void gemm_body(const float* __restrict__ X,
                                          const float* __restrict__ W,
                                          float* __restrict__ Y) {
    __shared__ float ws[64][64];
    __shared__ float xs[64][68];
    int tx = threadIdx.x, ty = threadIdx.y;
    int tid = ty * 16 + tx;

    for (int idx = tid; idx < 64 * 64; idx += 256) {
        int k = idx >> 6, j = idx & 63;
        ws[k][j] = (j < FOUT) ? W[k * FOUT + j] : 0.f;
    }
    int row0 = blockIdx.x * 64;
    for (int idx = tid; idx < 1024; idx += 256) {
        int r = idx >> 4, c = (idx & 15) * 4;
        int gr = row0 + r;
        float4 v = make_float4(0.f, 0.f, 0.f, 0.f);
        if (gr < N_NODES) v = *(const float4*)&X[gr * 64 + c];
        xs[r][c] = v.x; xs[r][c + 1] = v.y; xs[r][c + 2] = v.z; xs[r][c + 3] = v.w;
    }
    __syncthreads();

    float acc[4][4];
#pragma unroll
    for (int i = 0; i < 4; i++)
#pragma unroll
        for (int j = 0; j < 4; j++) acc[i][j] = 0.f;

#pragma unroll
    for (int k = 0; k < 64; k++) {
        float4 b = *(const float4*)&ws[k][tx * 4];
#pragma unroll
        for (int i = 0; i < 4; i++) {
            float a = xs[ty * 4 + i][k];
            acc[i][0] += a * b.x; acc[i][1] += a * b.y;
            acc[i][2] += a * b.z; acc[i][3] += a * b.w;
        }
    }

#pragma unroll
    for (int i = 0; i < 4; i++) {
        int gr = row0 + ty * 4 + i;
        if (gr >= N_NODES) continue;
#pragma unroll
        for (int j = 0; j < 4; j++) {
            int col = tx * 4 + j;
            if (col < FOUT) Y[gr * FOUT + col] = acc[i][j];
        }
    }
}

__global__ void k_gemm1(const float* __restrict__ X, const float* __restrict__ W) {
    gemm_body<64>(X, W, g_h1);
}
__global__ void k_gemm2(const float* __restrict__ W) {
    gemm_body<40>(g_hid, W, g_h2);
}

// ---------------------------------------------------------------------------
// layer-1 gather: warp per node. hid = relu(sum_{s->n} h1[s]*norm + h1[n]*d2 + b1)
// ---------------------------------------------------------------------------
__global__ void k_gather1(const float* __restrict__ b1) {
    int node = (blockIdx.x * blockDim.x + threadIdx.x) >> 5;
    int lane = threadIdx.x & 31;
    if (node >= N_NODES) return;
    float di = g_dinv[node];
    float d2 = di * di;
    float2 hv = *(const float2*)&g_h1[node * 64 + lane * 2];
    float ax = hv.x * d2, ay = hv.y * d2;
    int beg = g_off[node], end = g_off[node + 1];
    for (int p = beg; p < end; p++) {
        int s = g_srcl[p];
        float norm = g_dinv[s] * di;
        float2 v = *(const float2*)&g_h1[s * 64 + lane * 2];
        ax = fmaf(v.x, norm, ax);
        ay = fmaf(v.y, norm, ay);
    }
    float2 bv = ((const float2*)b1)[lane];
    ax = fmaxf(ax + bv.x, 0.f);
    ay = fmaxf(ay + bv.y, 0.f);
    *(float2*)&g_hid[node * 64 + lane * 2] = make_float2(ax, ay);
}

// ---------------------------------------------------------------------------
// layer-2 gather + bias + log_softmax: warp per node (40 cols, lanes 0..19)
// ---------------------------------------------------------------------------
__global__ void k_gather2(const float* __restrict__ b2, float* __restrict__ out) {
    int node = (blockIdx.x * blockDim.x + threadIdx.x) >> 5;
    int lane = threadIdx.x & 31;
    if (node >= N_NODES) return;
    float di = g_dinv[node];
    float d2 = di * di;
    bool act = lane < 20;
    float ax = 0.f, ay = 0.f;
    if (act) {
        float2 hv = *(const float2*)&g_h2[node * 40 + lane * 2];
        ax = hv.x * d2; ay = hv.y * d2;
    }
    int beg = g_off[node], end = g_off[node + 1];
    for (int p = beg; p < end; p++) {
        int s = g_srcl[p];
        float norm = g_dinv[s] * di;
        if (act) {
            float2 v = *(const float2*)&g_h2[s * 40 + lane * 2];
            ax = fmaf(v.x, norm, ax);
            ay = fmaf(v.y, norm, ay);
        }
    }
    if (act) {
        float2 bv = ((const float2*)b2)[lane];
        ax += bv.x; ay += bv.y;
    }
    // log_softmax across 40 values held by lanes 0..19
    float m = act ? fmaxf(ax, ay) : -INFINITY;
#pragma unroll
    for (int o = 16; o; o >>= 1) m = fmaxf(m, __shfl_xor_sync(0xffffffffu, m, o));
    float s = act ? (__expf(ax - m) + __expf(ay - m)) : 0.f;
#pragma unroll
    for (int o = 16; o; o >>= 1) s += __shfl_xor_sync(0xffffffffu, s, o);
    float ls = m + logf(s);
    if (act) *(float2*)&out[node * 40 + lane * 2] = make_float2(ax - ls, ay - ls);
}

// ---------------------------------------------------------------------------
// launch
// ---------------------------------------------------------------------------
extern "C" void kernel_launch(void* const* d_in, const int* in_sizes, int n_in,
                              void* d_out, int out_size) {
    const float* x  = (const float*)d_in[0];
    const void*  ei = d_in[1];
    const float* W1 = (const float*)d_in[2];
    const float* b1 = (const float*)d_in[3];
    const float* W2 = (const float*)d_in[4];
    const float* b2 = (const float*)d_in[5];
    float*       out = (float*)d_out;

    const int TB = 256;
    // dtype detect + CSR build + norms
    k_detect<<<1, 32>>>((const unsigned*)ei);
    k_zero_cnt<<<(N_NODES + TB - 1) / TB, TB>>>();
    k_count<<<(N_EDGES + TB - 1) / TB, TB>>>(ei);
    k_scan1<<<NB_SCAN, 256>>>();
    k_scan2<<<1, 512>>>();
    k_scan3<<<(N_NODES + TB - 1) / TB, TB>>>();
    k_fill<<<(N_EDGES + TB - 1) / TB, TB>>>(ei);
    // layer 1
    k_gemm1<<<(N_NODES + 63) / 64, dim3(16, 16)>>>(x, W1);
    k_gather1<<<(N_NODES * 32 + TB - 1) / TB, TB>>>(b1);
    // layer 2
    k_gemm2<<<(N_NODES + 63) / 64, dim3(16, 16)>>>(W2);
    k_gather2<<<(N_NODES * 32 + TB - 1) / TB, TB>>>(b2, out);
}

// round 7
// speedup vs baseline: 1.5373x; 1.5373x over previous
#include <cuda_runtime.h>
#include <math.h>

#define N_NODES 100000
#define N_EDGES 800000
#define NB_SCAN ((N_NODES + 255) / 256)   // 391

// ---- static device scratch (no allocations allowed) ----
__device__ int   g_is32;                 // 1 if edge_index delivered as int32
__device__ int   g_cnt [N_NODES];
__device__ int   g_off [N_NODES + 1];
__device__ int   g_cur [N_NODES];
__device__ int   g_srcl[N_EDGES];        // sources grouped by dst (CSR)
__device__ float g_dinv[N_NODES];
__device__ float g_h1  [N_NODES * 64];   // layer-1 pre-agg features
__device__ float g_hid [N_NODES * 64];   // relu'd hidden (layer-2 input)
__device__ float g_h2  [N_NODES * 40];   // layer-2 pre-agg features
__device__ int   g_bsum[512];
__device__ int   g_boff[512];

// ---------------------------------------------------------------------------
// zero counters + dtype detection (int64 values < 2^31 have zero high words)
// ---------------------------------------------------------------------------
__global__ void k_init(const unsigned* __restrict__ ei_raw) {
    int i = blockIdx.x * blockDim.x + threadIdx.x;
    if (i < N_NODES) g_cnt[i] = 0;
    if (blockIdx.x == 0 && threadIdx.x < 32) {
        unsigned v = ei_raw[2 * threadIdx.x + 1];
#pragma unroll
        for (int o = 16; o; o >>= 1) v |= __shfl_xor_sync(0xffffffffu, v, o);
        if (threadIdx.x == 0) g_is32 = (v != 0) ? 1 : 0;
    }
}

__device__ __forceinline__ int edge_at(const void* ei, int idx) {
    if (g_is32) return ((const int*)ei)[idx];
    return (int)((const long long*)ei)[idx];
}

// ---------------------------------------------------------------------------
// CSR build
// ---------------------------------------------------------------------------
__global__ void k_count(const void* __restrict__ ei) {
    int e = blockIdx.x * blockDim.x + threadIdx.x;
    if (e >= N_EDGES) return;
    int d = edge_at(ei, N_EDGES + e);
    if ((unsigned)d < N_NODES) atomicAdd(&g_cnt[d], 1);
}

// level-1 scan: 256 nodes per block; also computes dinv
__global__ void k_scan1() {
    int i = blockIdx.x * 256 + threadIdx.x;
    int lane = threadIdx.x & 31, wid = threadIdx.x >> 5;
    int v = (i < N_NODES) ? g_cnt[i] : 0;
    if (i < N_NODES) g_dinv[i] = rsqrtf((float)v + 1.0f);
    int x = v;
#pragma unroll
    for (int o = 1; o < 32; o <<= 1) {
        int y = __shfl_up_sync(0xffffffffu, x, o);
        if (lane >= o) x += y;
    }
    __shared__ int ws[8];
    if (lane == 31) ws[wid] = x;
    __syncthreads();
    if (wid == 0) {
        int s = (lane < 8) ? ws[lane] : 0;
#pragma unroll
        for (int o = 1; o < 8; o <<= 1) {
            int y = __shfl_up_sync(0xffffffffu, s, o);
            if (lane >= o) s += y;
        }
        if (lane < 8) ws[lane] = s;
    }
    __syncthreads();
    int incl = x + (wid ? ws[wid - 1] : 0);
    if (i < N_NODES) g_off[i] = incl - v;
    if (threadIdx.x == 255) g_bsum[blockIdx.x] = incl;
}

// level-2 scan: single block
__global__ void k_scan2() {
    int t = threadIdx.x, lane = t & 31, wid = t >> 5;
    int v = (t < NB_SCAN) ? g_bsum[t] : 0;
    int x = v;
#pragma unroll
    for (int o = 1; o < 32; o <<= 1) {
        int y = __shfl_up_sync(0xffffffffu, x, o);
        if (lane >= o) x += y;
    }
    __shared__ int ws[16];
    if (lane == 31) ws[wid] = x;
    __syncthreads();
    if (wid == 0) {
        int s = (lane < 16) ? ws[lane] : 0;
#pragma unroll
        for (int o = 1; o < 16; o <<= 1) {
            int y = __shfl_up_sync(0xffffffffu, s, o);
            if (lane >= o) s += y;
        }
        if (lane < 16) ws[lane] = s;
    }
    __syncthreads();
    int incl = x + (wid ? ws[wid - 1] : 0);
    if (t < 512) g_boff[t] = incl - v;
}

// finalize offsets + cursors
__global__ void k_scan3() {
    int i = blockIdx.x * blockDim.x + threadIdx.x;
    if (i < N_NODES) {
        int o = g_off[i] + g_boff[i >> 8];
        g_off[i] = o;
        g_cur[i] = o;
    }
    if (i == 0) g_off[N_NODES] = N_EDGES;
}

__global__ void k_fill(const void* __restrict__ ei) {
    int e = blockIdx.x * blockDim.x + threadIdx.x;
    if (e >= N_EDGES) return;
    int s = edge_at(ei, e);
    int d = edge_at(ei, N_EDGES + e);
    if ((unsigned)d >= N_NODES || (unsigned)s >= N_NODES) return;
    int p = atomicAdd(&g_cur[d], 1);
    if ((unsigned)p < N_EDGES) g_srcl[p] = s;
}

// ---------------------------------------------------------------------------
// GEMM body: Y[n,FOUT] = X[n,64] @ W[64,FOUT]
// TROWS-row tile, block (FOUT/4, TROWS/8), thread computes 8 rows x 4 cols.
// X tile stored K-major (xs[k][r]); per-warp reads are broadcast/conflict-free.
// X and Y are DEVICE-SYMBOL references passed from device code (wrappers) —
// never host-decayed __device__ pointers (that was the R4/R6 bug: host shadow
// address + ATS made GEMM output silently land in host memory).
// ---------------------------------------------------------------------------
template <int FOUT, int TROWS>
__device__ __forceinline__ void gemm_body(const float* __restrict__ X,
                                          const float* __restrict__ W,
                                          float* __restrict__ Y) {
    __shared__ float ws[64][FOUT];
    __shared__ float xs[64][TROWS + 4];    // (TROWS+4)*4B is a 16B multiple
    const int NT = (FOUT / 4) * (TROWS / 8);
    int tx = threadIdx.x, ty = threadIdx.y;
    int tid = ty * (FOUT / 4) + tx;
    int row0 = blockIdx.x * TROWS;

    for (int idx = tid; idx < 64 * (FOUT / 4); idx += NT) {
        int k = idx / (FOUT / 4), j4 = idx % (FOUT / 4);
        *(float4*)&ws[k][j4 * 4] = *(const float4*)&W[k * FOUT + j4 * 4];
    }
    // r-major mapping: consecutive threads write consecutive r -> conflict-free STS
    for (int idx = tid; idx < TROWS * 16; idx += NT) {
        int r = idx & (TROWS - 1), c4 = idx / TROWS;
        int gr = row0 + r;
        float4 v = make_float4(0.f, 0.f, 0.f, 0.f);
        if (gr < N_NODES) v = *(const float4*)&X[gr * 64 + c4 * 4];
        xs[c4 * 4 + 0][r] = v.x; xs[c4 * 4 + 1][r] = v.y;
        xs[c4 * 4 + 2][r] = v.z; xs[c4 * 4 + 3][r] = v.w;
    }
    __syncthreads();

    float acc[8][4];
#pragma unroll
    for (int i = 0; i < 8; i++)
#pragma unroll
        for (int j = 0; j < 4; j++) acc[i][j] = 0.f;

    int rbase = ty * 8;
#pragma unroll 8
    for (int k = 0; k < 64; k++) {
        float4 b  = *(const float4*)&ws[k][tx * 4];
        float4 a0 = *(const float4*)&xs[k][rbase];
        float4 a1 = *(const float4*)&xs[k][rbase + 4];
        float a[8] = {a0.x, a0.y, a0.z, a0.w, a1.x, a1.y, a1.z, a1.w};
#pragma unroll
        for (int i = 0; i < 8; i++) {
            acc[i][0] = fmaf(a[i], b.x, acc[i][0]);
            acc[i][1] = fmaf(a[i], b.y, acc[i][1]);
            acc[i][2] = fmaf(a[i], b.z, acc[i][2]);
            acc[i][3] = fmaf(a[i], b.w, acc[i][3]);
        }
    }

#pragma unroll
    for (int i = 0; i < 8; i++) {
        int gr = row0 + rbase + i;
        if (gr < N_NODES)
            *(float4*)&Y[gr * FOUT + tx * 4] =
                make_float4(acc[i][0], acc[i][1], acc[i][2], acc[i][3]);
    }
}

// wrappers: bind device symbols from DEVICE code
__global__ void k_gemm1(const float* __restrict__ X, const float* __restrict__ W) {
    gemm_body<64, 64>(X, W, g_h1);
}
__global__ void k_gemm2(const float* __restrict__ W) {
    gemm_body<40, 128>(g_hid, W, g_h2);
}

// ---------------------------------------------------------------------------
// layer-1 gather: warp per node, 2-edge unroll.
// hid = relu(sum h1[s]*norm + h1[n]*d2 + b1)
// ---------------------------------------------------------------------------
__global__ void k_gather1(const float* __restrict__ b1) {
    int node = (blockIdx.x * blockDim.x + threadIdx.x) >> 5;
    int lane = threadIdx.x & 31;
    if (node >= N_NODES) return;
    float di = g_dinv[node];
    float d2 = di * di;
    float2 hv = *(const float2*)&g_h1[node * 64 + lane * 2];
    float ax = hv.x * d2, ay = hv.y * d2;
    float bx = 0.f, by = 0.f;
    int beg = g_off[node], end = g_off[node + 1];
    int p = beg;
    for (; p + 2 <= end; p += 2) {
        int s0 = g_srcl[p], s1 = g_srcl[p + 1];
        float n0 = g_dinv[s0] * di, n1 = g_dinv[s1] * di;
        float2 v0 = *(const float2*)&g_h1[s0 * 64 + lane * 2];
        float2 v1 = *(const float2*)&g_h1[s1 * 64 + lane * 2];
        ax = fmaf(v0.x, n0, ax); ay = fmaf(v0.y, n0, ay);
        bx = fmaf(v1.x, n1, bx); by = fmaf(v1.y, n1, by);
    }
    if (p < end) {
        int s = g_srcl[p];
        float n = g_dinv[s] * di;
        float2 v = *(const float2*)&g_h1[s * 64 + lane * 2];
        ax = fmaf(v.x, n, ax); ay = fmaf(v.y, n, ay);
    }
    ax += bx; ay += by;
    float2 bv = ((const float2*)b1)[lane];
    ax = fmaxf(ax + bv.x, 0.f);
    ay = fmaxf(ay + bv.y, 0.f);
    *(float2*)&g_hid[node * 64 + lane * 2] = make_float2(ax, ay);
}

// ---------------------------------------------------------------------------
// layer-2 gather + bias + log_softmax: warp per node (lanes 0..19 active)
// ---------------------------------------------------------------------------
__global__ void k_gather2(const float* __restrict__ b2, float* __restrict__ out) {
    int node = (blockIdx.x * blockDim.x + threadIdx.x) >> 5;
    int lane = threadIdx.x & 31;
    if (node >= N_NODES) return;
    float di = g_dinv[node];
    float d2 = di * di;
    int cl = (lane < 20) ? lane : 19;      // clamp: inactive lanes do harmless dup work
    bool act = lane < 20;
    float2 hv = *(const float2*)&g_h2[node * 40 + cl * 2];
    float ax = hv.x * d2, ay = hv.y * d2;
    float bx = 0.f, by = 0.f;
    int beg = g_off[node], end = g_off[node + 1];
    int p = beg;
    for (; p + 2 <= end; p += 2) {
        int s0 = g_srcl[p], s1 = g_srcl[p + 1];
        float n0 = g_dinv[s0] * di, n1 = g_dinv[s1] * di;
        float2 v0 = *(const float2*)&g_h2[s0 * 40 + cl * 2];
        float2 v1 = *(const float2*)&g_h2[s1 * 40 + cl * 2];
        ax = fmaf(v0.x, n0, ax); ay = fmaf(v0.y, n0, ay);
        bx = fmaf(v1.x, n1, bx); by = fmaf(v1.y, n1, by);
    }
    if (p < end) {
        int s = g_srcl[p];
        float n = g_dinv[s] * di;
        float2 v = *(const float2*)&g_h2[s * 40 + cl * 2];
        ax = fmaf(v.x, n, ax); ay = fmaf(v.y, n, ay);
    }
    ax += bx; ay += by;
    float2 bv = ((const float2*)b2)[cl];
    ax += bv.x; ay += bv.y;
    // log_softmax over the 40 values in lanes 0..19
    float m = act ? fmaxf(ax, ay) : -INFINITY;
#pragma unroll
    for (int o = 16; o; o >>= 1) m = fmaxf(m, __shfl_xor_sync(0xffffffffu, m, o));
    float s = act ? (__expf(ax - m) + __expf(ay - m)) : 0.f;
#pragma unroll
    for (int o = 16; o; o >>= 1) s += __shfl_xor_sync(0xffffffffu, s, o);
    float ls = m + logf(s);
    if (act) *(float2*)&out[node * 40 + lane * 2] = make_float2(ax - ls, ay - ls);
}

// ---------------------------------------------------------------------------
// launch
// ---------------------------------------------------------------------------
extern "C" void kernel_launch(void* const* d_in, const int* in_sizes, int n_in,
                              void* d_out, int out_size) {
    const float* x  = (const float*)d_in[0];
    const void*  ei = d_in[1];
    const float* W1 = (const float*)d_in[2];
    const float* b1 = (const float*)d_in[3];
    const float* W2 = (const float*)d_in[4];
    const float* b2 = (const float*)d_in[5];
    float*       out = (float*)d_out;

    const int TB = 256;
    k_init<<<(N_NODES + TB - 1) / TB, TB>>>((const unsigned*)ei);
    k_count<<<(N_EDGES + TB - 1) / TB, TB>>>(ei);
    k_scan1<<<NB_SCAN, 256>>>();
    k_scan2<<<1, 512>>>();
    k_scan3<<<(N_NODES + TB - 1) / TB, TB>>>();
    k_fill<<<(N_EDGES + TB - 1) / TB, TB>>>(ei);
    // layer 1: 64-row tiles, block (16,8)=128 thr, smem 33,792 B
    k_gemm1<<<(N_NODES + 63) / 64, dim3(16, 8)>>>(x, W1);
    k_gather1<<<(N_NODES * 32 + TB - 1) / TB, TB>>>(b1);
    // layer 2: 128-row tiles, block (10,16)=160 thr, smem 44,032 B
    k_gemm2<<<(N_NODES + 127) / 128, dim3(10, 16)>>>(W2);
    k_gather2<<<(N_NODES * 32 + TB - 1) / TB, TB>>>(b2, out);
}